// round 6
// baseline (speedup 1.0000x reference)
#include <cuda_runtime.h>
#include <mma.h>
#include <math.h>

using namespace nvcuda;

// ---------------- problem constants ----------------
#define Bsz   16
#define Nseq  784
#define DIM   512
#define Hh    8
#define KDIM  64
#define VDIM  256
#define RESW  28
#define QKVO  3072      // (2*64+256)*8
#define Mrows (Bsz*Nseq) // 12544
#define EPSV  1e-5f
#define SCALEV 0.125f    // 64^-0.5
#define LDA   36        // smem row stride for BN-GEMM tiles

// ---------------- scratch (device globals; no allocs allowed) ----------------
// Q, K stored TRANSPOSED per (b,h):  [bh][d][n]
__device__ float g_Q[(size_t)Bsz*Hh*KDIM*Nseq];
__device__ float g_K[(size_t)Bsz*Hh*KDIM*Nseq];
__device__ float g_V[(size_t)Bsz*Hh*Nseq*VDIM];
__device__ float g_AO[(size_t)Bsz*Nseq*Hh*VDIM];

// =====================================================================
// GEMM 1 (TF32 WMMA): qkv = BN(x @ qkv_w^T) -> scatter to Q^T/K^T/V
// (verified round 5, unchanged)
// =====================================================================
__global__ __launch_bounds__(256) void gemm_qkv_kernel(
    const float* __restrict__ A, const float* __restrict__ W,
    const float* __restrict__ gamma, const float* __restrict__ beta,
    const float* __restrict__ mean, const float* __restrict__ var)
{
    __shared__ float As[128][LDA];
    __shared__ float Bs[128][LDA];
    __shared__ float stage[8][16 * 20];

    const int K  = DIM;
    const int bm = blockIdx.x * 128;
    const int bn = blockIdx.y * 128;
    const int tid  = threadIdx.x;
    const int wid  = tid >> 5;
    const int lane = tid & 31;
    const int wm = wid & 3;
    const int wn = wid >> 2;

    wmma::fragment<wmma::accumulator, 16, 16, 8, float> cf[2][4];
#pragma unroll
    for (int mi = 0; mi < 2; mi++)
#pragma unroll
        for (int ni = 0; ni < 4; ni++)
            wmma::fill_fragment(cf[mi][ni], 0.f);

    for (int k0 = 0; k0 < K; k0 += 32) {
        __syncthreads();
#pragma unroll
        for (int i = 0; i < 4; i++) {
            int s   = tid + i * 256;
            int row = s >> 3;
            int c4  = (s & 7) << 2;
            float4 av = *(const float4*)(A + (size_t)(bm + row) * K + k0 + c4);
            float4 wv = *(const float4*)(W + (size_t)(bn + row) * K + k0 + c4);
            As[row][c4+0] = wmma::__float_to_tf32(av.x);
            As[row][c4+1] = wmma::__float_to_tf32(av.y);
            As[row][c4+2] = wmma::__float_to_tf32(av.z);
            As[row][c4+3] = wmma::__float_to_tf32(av.w);
            Bs[row][c4+0] = wmma::__float_to_tf32(wv.x);
            Bs[row][c4+1] = wmma::__float_to_tf32(wv.y);
            Bs[row][c4+2] = wmma::__float_to_tf32(wv.z);
            Bs[row][c4+3] = wmma::__float_to_tf32(wv.w);
        }
        __syncthreads();

#pragma unroll
        for (int kk = 0; kk < 32; kk += 8) {
            wmma::fragment<wmma::matrix_b, 16, 16, 8, wmma::precision::tf32, wmma::col_major> bf[4];
#pragma unroll
            for (int ni = 0; ni < 4; ni++)
                wmma::load_matrix_sync(bf[ni], &Bs[wn * 64 + ni * 16][kk], LDA);
#pragma unroll
            for (int mi = 0; mi < 2; mi++) {
                wmma::fragment<wmma::matrix_a, 16, 16, 8, wmma::precision::tf32, wmma::row_major> af;
                wmma::load_matrix_sync(af, &As[wm * 32 + mi * 16][kk], LDA);
#pragma unroll
                for (int ni = 0; ni < 4; ni++)
                    wmma::mma_sync(cf[mi][ni], af, bf[ni], cf[mi][ni]);
            }
        }
    }

    float* st = &stage[wid][0];
    const int r0 = lane >> 3;
    const int c0 = (lane & 7) << 1;
#pragma unroll
    for (int mi = 0; mi < 2; mi++)
#pragma unroll
        for (int ni = 0; ni < 4; ni++) {
            wmma::store_matrix_sync(st, cf[mi][ni], 20, wmma::mem_row_major);
            __syncwarp();
#pragma unroll
            for (int rr = 0; rr < 4; rr++) {
                int r = r0 + rr * 4;
                int row = bm + wm * 32 + mi * 16 + r;
                int b = row / Nseq;
                int n = row - b * Nseq;
#pragma unroll
                for (int cc = 0; cc < 2; cc++) {
                    int c = c0 + cc;
                    int col = bn + wn * 64 + ni * 16 + c;
                    float sc = gamma[col] * rsqrtf(var[col] + EPSV);
                    float sh = beta[col] - mean[col] * sc;
                    float val = st[r * 20 + c] * sc + sh;
                    int h  = col / 384;
                    int rrv = col - h * 384;
                    int bh = b * Hh + h;
                    if (rrv < KDIM)
                        g_Q[((size_t)bh * KDIM + rrv) * Nseq + n] = val;
                    else if (rrv < 2 * KDIM)
                        g_K[((size_t)bh * KDIM + (rrv - KDIM)) * Nseq + n] = val;
                    else
                        g_V[((size_t)bh * Nseq + n) * VDIM + (rrv - 2 * KDIM)] = val;
                }
            }
            __syncwarp();
        }
}

// =====================================================================
// Attention v4 (TF32 WMMA): per CTA 64 q-rows, 13 key tiles of 64.
// S = Q.K^T on tensor cores -> smem -> SIMT softmax (no max subtraction;
// num/den accumulation, den from tf32-rounded P) -> PV on tensor cores
// with persistent O fragments. SiLU fused. smem = 92480 B.
// =====================================================================
#define LDQ 72
#define LDV 132
#define ATT_SMEM (23120 * 4)

__global__ __launch_bounds__(256, 2) void attn_kernel(const float* __restrict__ biases)
{
    extern __shared__ float smem[];
    float* Qst = smem;            // [64][LDQ]  Qst[d][row] (tf32)
    float* Kst = smem + 4608;     // [64][LDQ]  Kst[d][key] (tf32)
    float* SPs = smem + 9216;     // [64][LDQ]  S then P (rows x keys)
    float* Vs  = smem + 13824;    // [64][LDV]  V chunk (keys x 128 vcols); also O staging
    float* brow= smem + 22272;    // 784
    float* den = smem + 23056;    // 64

    const int bh = blockIdx.y;
    const int b  = bh >> 3;
    const int h  = bh & 7;
    const int n0 = blockIdx.x * 64;
    const int tid  = threadIdx.x;
    const int wid  = tid >> 5;
    const int wm = wid >> 1;      // row group (16 rows)
    const int wn = wid & 1;       // col group

    const float* Qb = g_Q + (size_t)bh * KDIM * Nseq;
    const float* Kb = g_K + (size_t)bh * KDIM * Nseq;
    const float* Vb = g_V + (size_t)bh * Nseq * VDIM;

    for (int i = tid; i < Nseq; i += 256) brow[i] = biases[h * Nseq + i];
    if (tid < 64) den[tid] = 0.f;

    // load Q^T tile (tf32): Qst[d][r]
#pragma unroll
    for (int i = 0; i < 4; i++) {
        int s  = tid + i * 256;
        int d  = s >> 4;
        int q4 = (s & 15) << 2;
        float4 v = (n0 + q4 < Nseq)
                 ? *(const float4*)(Qb + (size_t)d * Nseq + n0 + q4)
                 : make_float4(0.f, 0.f, 0.f, 0.f);
        Qst[d * LDQ + q4 + 0] = wmma::__float_to_tf32(v.x);
        Qst[d * LDQ + q4 + 1] = wmma::__float_to_tf32(v.y);
        Qst[d * LDQ + q4 + 2] = wmma::__float_to_tf32(v.z);
        Qst[d * LDQ + q4 + 3] = wmma::__float_to_tf32(v.w);
    }

    // softmax mapping: thread t -> row r = t>>2, cols (t&3)*16..+15
    const int smr = tid >> 2;
    const int smc = (tid & 3) << 4;
    int rn = n0 + smr;
    int rc = (rn < Nseq) ? rn : (Nseq - 1);
    const int ry = rc / RESW;
    const int rx = rc - ry * RESW;

    // persistent O accumulators: rows wm*16..+15, vcols chunk c: wn*64 + f*16
    wmma::fragment<wmma::accumulator, 16, 16, 8, float> of[2][4];
#pragma unroll
    for (int c = 0; c < 2; c++)
#pragma unroll
        for (int f = 0; f < 4; f++)
            wmma::fill_fragment(of[c][f], 0.f);

    const int NTILE = (Nseq + 63) / 64;   // 13
    for (int kt = 0; kt < NTILE; kt++) {
        const int mbase = kt * 64;
        __syncthreads();   // prior tile's PV reads done

        // load K^T tile (tf32): Kst[d][m]
#pragma unroll
        for (int i = 0; i < 4; i++) {
            int s  = tid + i * 256;
            int d  = s >> 4;
            int q4 = (s & 15) << 2;
            float4 v = (mbase + q4 < Nseq)
                     ? *(const float4*)(Kb + (size_t)d * Nseq + mbase + q4)
                     : make_float4(0.f, 0.f, 0.f, 0.f);
            Kst[d * LDQ + q4 + 0] = wmma::__float_to_tf32(v.x);
            Kst[d * LDQ + q4 + 1] = wmma::__float_to_tf32(v.y);
            Kst[d * LDQ + q4 + 2] = wmma::__float_to_tf32(v.z);
            Kst[d * LDQ + q4 + 3] = wmma::__float_to_tf32(v.w);
        }
        __syncthreads();

        // ---- S = Q.K^T : warp (wm,wn) -> S[wm*16..+15][wn*32..+31] ----
        {
            wmma::fragment<wmma::accumulator, 16, 16, 8, float> sf[2];
            wmma::fill_fragment(sf[0], 0.f);
            wmma::fill_fragment(sf[1], 0.f);
#pragma unroll
            for (int kk = 0; kk < KDIM; kk += 8) {
                wmma::fragment<wmma::matrix_a, 16, 16, 8, wmma::precision::tf32, wmma::col_major> af;
                wmma::load_matrix_sync(af, &Qst[kk * LDQ + wm * 16], LDQ);
#pragma unroll
                for (int f = 0; f < 2; f++) {
                    wmma::fragment<wmma::matrix_b, 16, 16, 8, wmma::precision::tf32, wmma::row_major> bf;
                    wmma::load_matrix_sync(bf, &Kst[kk * LDQ + wn * 32 + f * 16], LDQ);
                    wmma::mma_sync(sf[f], af, bf, sf[f]);
                }
            }
#pragma unroll
            for (int f = 0; f < 2; f++)
                wmma::store_matrix_sync(&SPs[(wm * 16) * LDQ + wn * 32 + f * 16],
                                        sf[f], LDQ, wmma::mem_row_major);
        }
        __syncthreads();

        // ---- softmax (no max subtraction): P = exp(S*scale + bias) ----
        {
            float psum = 0.f;
#pragma unroll
            for (int c = 0; c < 16; c++) {
                int m = mbase + smc + c;
                float p = 0.f;
                if (m < Nseq) {
                    int my = m / RESW;
                    int mx = m - my * RESW;
                    int dy = abs(ry - my), dx = abs(rx - mx);
                    float sv = SPs[smr * LDQ + smc + c] * SCALEV + brow[dy * RESW + dx];
                    p = wmma::__float_to_tf32(__expf(sv));
                }
                SPs[smr * LDQ + smc + c] = p;
                psum += p;
            }
            psum += __shfl_xor_sync(0xffffffffu, psum, 1);
            psum += __shfl_xor_sync(0xffffffffu, psum, 2);
            if ((tid & 3) == 0) den[smr] += psum;
        }
        __syncthreads();

        // ---- PV: O[wm*16..+15][c*128 + wn*64 + f*16] += P.V ----
#pragma unroll
        for (int c = 0; c < 2; c++) {
#pragma unroll
            for (int i = 0; i < 8; i++) {
                int s  = tid + i * 256;
                int mm = s >> 5;
                int c4 = (s & 31) << 2;
                float4 v = (mbase + mm < Nseq)
                         ? *(const float4*)(Vb + (size_t)(mbase + mm) * VDIM + c * 128 + c4)
                         : make_float4(0.f, 0.f, 0.f, 0.f);
                Vs[mm * LDV + c4 + 0] = wmma::__float_to_tf32(v.x);
                Vs[mm * LDV + c4 + 1] = wmma::__float_to_tf32(v.y);
                Vs[mm * LDV + c4 + 2] = wmma::__float_to_tf32(v.z);
                Vs[mm * LDV + c4 + 3] = wmma::__float_to_tf32(v.w);
            }
            __syncthreads();
#pragma unroll
            for (int kk = 0; kk < 64; kk += 8) {
                wmma::fragment<wmma::matrix_a, 16, 16, 8, wmma::precision::tf32, wmma::row_major> pf;
                wmma::load_matrix_sync(pf, &SPs[(wm * 16) * LDQ + kk], LDQ);
#pragma unroll
                for (int f = 0; f < 4; f++) {
                    wmma::fragment<wmma::matrix_b, 16, 16, 8, wmma::precision::tf32, wmma::row_major> bf;
                    wmma::load_matrix_sync(bf, &Vs[kk * LDV + wn * 64 + f * 16], LDV);
                    wmma::mma_sync(of[c][f], pf, bf, of[c][f]);
                }
            }
            if (c == 0) __syncthreads();
        }
    }

    // ---- epilogue: stage O, normalize by den, SiLU, store ----
#pragma unroll
    for (int c = 0; c < 2; c++) {
        __syncthreads();
#pragma unroll
        for (int f = 0; f < 4; f++)
            wmma::store_matrix_sync(&Vs[(wm * 16) * LDV + wn * 64 + f * 16],
                                    of[c][f], LDV, wmma::mem_row_major);
        __syncthreads();
        int n = n0 + smr;
        if (n < Nseq) {
            float inv = 1.f / den[smr];
            size_t base = ((size_t)b * Nseq + n) * (Hh * VDIM) + h * VDIM + c * 128;
#pragma unroll
            for (int j = 0; j < 8; j++) {
                int col = ((tid & 3) << 2) + j * 16;
                float4 v = *(const float4*)&Vs[smr * LDV + col];
                float t;
                t = v.x * inv; v.x = t / (1.f + __expf(-t));
                t = v.y * inv; v.y = t / (1.f + __expf(-t));
                t = v.z * inv; v.z = t / (1.f + __expf(-t));
                t = v.w * inv; v.w = t / (1.f + __expf(-t));
                *(float4*)(g_AO + base + col) = v;
            }
        }
    }
}

// =====================================================================
// GEMM 2 (TF32 WMMA): out = BN(silu_out @ proj_w^T)  (round 5, unchanged)
// =====================================================================
__global__ __launch_bounds__(256) void gemm_proj_kernel(
    const float* __restrict__ W,
    const float* __restrict__ gamma, const float* __restrict__ beta,
    const float* __restrict__ mean, const float* __restrict__ var,
    float* __restrict__ out)
{
    __shared__ float As[128][LDA];
    __shared__ float Bs[128][LDA];
    __shared__ float stage[8][16 * 20];

    const int K  = Hh * VDIM;   // 2048
    const float* A = g_AO;
    const int bm = blockIdx.x * 128;
    const int bn = blockIdx.y * 128;
    const int tid  = threadIdx.x;
    const int wid  = tid >> 5;
    const int lane = tid & 31;
    const int wm = wid & 3;
    const int wn = wid >> 2;

    wmma::fragment<wmma::accumulator, 16, 16, 8, float> cf[2][4];
#pragma unroll
    for (int mi = 0; mi < 2; mi++)
#pragma unroll
        for (int ni = 0; ni < 4; ni++)
            wmma::fill_fragment(cf[mi][ni], 0.f);

    for (int k0 = 0; k0 < K; k0 += 32) {
        __syncthreads();
#pragma unroll
        for (int i = 0; i < 4; i++) {
            int s   = tid + i * 256;
            int row = s >> 3;
            int c4  = (s & 7) << 2;
            float4 av = *(const float4*)(A + (size_t)(bm + row) * K + k0 + c4);
            float4 wv = *(const float4*)(W + (size_t)(bn + row) * K + k0 + c4);
            As[row][c4+0] = wmma::__float_to_tf32(av.x);
            As[row][c4+1] = wmma::__float_to_tf32(av.y);
            As[row][c4+2] = wmma::__float_to_tf32(av.z);
            As[row][c4+3] = wmma::__float_to_tf32(av.w);
            Bs[row][c4+0] = wmma::__float_to_tf32(wv.x);
            Bs[row][c4+1] = wmma::__float_to_tf32(wv.y);
            Bs[row][c4+2] = wmma::__float_to_tf32(wv.z);
            Bs[row][c4+3] = wmma::__float_to_tf32(wv.w);
        }
        __syncthreads();

#pragma unroll
        for (int kk = 0; kk < 32; kk += 8) {
            wmma::fragment<wmma::matrix_b, 16, 16, 8, wmma::precision::tf32, wmma::col_major> bf[4];
#pragma unroll
            for (int ni = 0; ni < 4; ni++)
                wmma::load_matrix_sync(bf[ni], &Bs[wn * 64 + ni * 16][kk], LDA);
#pragma unroll
            for (int mi = 0; mi < 2; mi++) {
                wmma::fragment<wmma::matrix_a, 16, 16, 8, wmma::precision::tf32, wmma::row_major> af;
                wmma::load_matrix_sync(af, &As[wm * 32 + mi * 16][kk], LDA);
#pragma unroll
                for (int ni = 0; ni < 4; ni++)
                    wmma::mma_sync(cf[mi][ni], af, bf[ni], cf[mi][ni]);
            }
        }
    }

    float* st = &stage[wid][0];
    const int r0 = lane >> 3;
    const int c0 = (lane & 7) << 1;
#pragma unroll
    for (int mi = 0; mi < 2; mi++)
#pragma unroll
        for (int ni = 0; ni < 4; ni++) {
            wmma::store_matrix_sync(st, cf[mi][ni], 20, wmma::mem_row_major);
            __syncwarp();
#pragma unroll
            for (int rr = 0; rr < 4; rr++) {
                int r = r0 + rr * 4;
                int row = bm + wm * 32 + mi * 16 + r;
#pragma unroll
                for (int cc = 0; cc < 2; cc++) {
                    int c = c0 + cc;
                    int col = bn + wn * 64 + ni * 16 + c;
                    float sc = gamma[col] * rsqrtf(var[col] + EPSV);
                    float sh = beta[col] - mean[col] * sc;
                    out[(size_t)row * DIM + col] = st[r * 20 + c] * sc + sh;
                }
            }
            __syncwarp();
        }
}

// =====================================================================
extern "C" void kernel_launch(void* const* d_in, const int* in_sizes, int n_in,
                              void* d_out, int out_size)
{
    const float* x          = (const float*)d_in[0];
    const float* qkv_w      = (const float*)d_in[1];
    const float* qkv_gamma  = (const float*)d_in[2];
    const float* qkv_beta   = (const float*)d_in[3];
    const float* qkv_mean   = (const float*)d_in[4];
    const float* qkv_var    = (const float*)d_in[5];
    const float* att_bias   = (const float*)d_in[6];
    const float* proj_w     = (const float*)d_in[7];
    const float* proj_gamma = (const float*)d_in[8];
    const float* proj_beta  = (const float*)d_in[9];
    const float* proj_mean  = (const float*)d_in[10];
    const float* proj_var   = (const float*)d_in[11];
    // d_in[12] = bias_idxs: computed analytically in-kernel

    cudaFuncSetAttribute(attn_kernel,
                         cudaFuncAttributeMaxDynamicSharedMemorySize, ATT_SMEM);

    gemm_qkv_kernel<<<dim3(Mrows / 128, QKVO / 128), 256>>>(
        x, qkv_w, qkv_gamma, qkv_beta, qkv_mean, qkv_var);

    attn_kernel<<<dim3((Nseq + 63) / 64, Bsz * Hh), 256, ATT_SMEM>>>(att_bias);

    gemm_proj_kernel<<<dim3(Mrows / 128, DIM / 128), 256>>>(
        proj_w, proj_gamma, proj_beta, proj_mean, proj_var, (float*)d_out);
}

// round 7
// speedup vs baseline: 1.1724x; 1.1724x over previous
#include <cuda_runtime.h>
#include <mma.h>
#include <math.h>

using namespace nvcuda;

// ---------------- problem constants ----------------
#define Bsz   16
#define Nseq  784
#define DIM   512
#define Hh    8
#define KDIM  64
#define VDIM  256
#define RESW  28
#define QKVO  3072      // (2*64+256)*8
#define Mrows (Bsz*Nseq) // 12544
#define EPSV  1e-5f
#define SCALEV 0.125f    // 64^-0.5
#define LDA   36        // smem row stride for BN-GEMM tiles

// ---------------- scratch (device globals; no allocs allowed) ----------------
// Q, K stored TRANSPOSED per (b,h):  [bh][d][n]
__device__ float g_Q[(size_t)Bsz*Hh*KDIM*Nseq];
__device__ float g_K[(size_t)Bsz*Hh*KDIM*Nseq];
__device__ float g_V[(size_t)Bsz*Hh*Nseq*VDIM];
__device__ float g_AO[(size_t)Bsz*Nseq*Hh*VDIM];

// =====================================================================
// GEMM 1 (TF32 WMMA): qkv = BN(x @ qkv_w^T) -> scatter to Q^T/K^T/V
// (verified round 5, unchanged)
// =====================================================================
__global__ __launch_bounds__(256) void gemm_qkv_kernel(
    const float* __restrict__ A, const float* __restrict__ W,
    const float* __restrict__ gamma, const float* __restrict__ beta,
    const float* __restrict__ mean, const float* __restrict__ var)
{
    __shared__ float As[128][LDA];
    __shared__ float Bs[128][LDA];
    __shared__ float stage[8][16 * 20];

    const int K  = DIM;
    const int bm = blockIdx.x * 128;
    const int bn = blockIdx.y * 128;
    const int tid  = threadIdx.x;
    const int wid  = tid >> 5;
    const int lane = tid & 31;
    const int wm = wid & 3;
    const int wn = wid >> 2;

    wmma::fragment<wmma::accumulator, 16, 16, 8, float> cf[2][4];
#pragma unroll
    for (int mi = 0; mi < 2; mi++)
#pragma unroll
        for (int ni = 0; ni < 4; ni++)
            wmma::fill_fragment(cf[mi][ni], 0.f);

    for (int k0 = 0; k0 < K; k0 += 32) {
        __syncthreads();
#pragma unroll
        for (int i = 0; i < 4; i++) {
            int s   = tid + i * 256;
            int row = s >> 3;
            int c4  = (s & 7) << 2;
            float4 av = *(const float4*)(A + (size_t)(bm + row) * K + k0 + c4);
            float4 wv = *(const float4*)(W + (size_t)(bn + row) * K + k0 + c4);
            As[row][c4+0] = wmma::__float_to_tf32(av.x);
            As[row][c4+1] = wmma::__float_to_tf32(av.y);
            As[row][c4+2] = wmma::__float_to_tf32(av.z);
            As[row][c4+3] = wmma::__float_to_tf32(av.w);
            Bs[row][c4+0] = wmma::__float_to_tf32(wv.x);
            Bs[row][c4+1] = wmma::__float_to_tf32(wv.y);
            Bs[row][c4+2] = wmma::__float_to_tf32(wv.z);
            Bs[row][c4+3] = wmma::__float_to_tf32(wv.w);
        }
        __syncthreads();

#pragma unroll
        for (int kk = 0; kk < 32; kk += 8) {
            wmma::fragment<wmma::matrix_b, 16, 16, 8, wmma::precision::tf32, wmma::col_major> bf[4];
#pragma unroll
            for (int ni = 0; ni < 4; ni++)
                wmma::load_matrix_sync(bf[ni], &Bs[wn * 64 + ni * 16][kk], LDA);
#pragma unroll
            for (int mi = 0; mi < 2; mi++) {
                wmma::fragment<wmma::matrix_a, 16, 16, 8, wmma::precision::tf32, wmma::row_major> af;
                wmma::load_matrix_sync(af, &As[wm * 32 + mi * 16][kk], LDA);
#pragma unroll
                for (int ni = 0; ni < 4; ni++)
                    wmma::mma_sync(cf[mi][ni], af, bf[ni], cf[mi][ni]);
            }
        }
    }

    float* st = &stage[wid][0];
    const int r0 = lane >> 3;
    const int c0 = (lane & 7) << 1;
#pragma unroll
    for (int mi = 0; mi < 2; mi++)
#pragma unroll
        for (int ni = 0; ni < 4; ni++) {
            wmma::store_matrix_sync(st, cf[mi][ni], 20, wmma::mem_row_major);
            __syncwarp();
#pragma unroll
            for (int rr = 0; rr < 4; rr++) {
                int r = r0 + rr * 4;
                int row = bm + wm * 32 + mi * 16 + r;
                int b = row / Nseq;
                int n = row - b * Nseq;
#pragma unroll
                for (int cc = 0; cc < 2; cc++) {
                    int c = c0 + cc;
                    int col = bn + wn * 64 + ni * 16 + c;
                    float sc = gamma[col] * rsqrtf(var[col] + EPSV);
                    float sh = beta[col] - mean[col] * sc;
                    float val = st[r * 20 + c] * sc + sh;
                    int h  = col / 384;
                    int rrv = col - h * 384;
                    int bh = b * Hh + h;
                    if (rrv < KDIM)
                        g_Q[((size_t)bh * KDIM + rrv) * Nseq + n] = val;
                    else if (rrv < 2 * KDIM)
                        g_K[((size_t)bh * KDIM + (rrv - KDIM)) * Nseq + n] = val;
                    else
                        g_V[((size_t)bh * Nseq + n) * VDIM + (rrv - 2 * KDIM)] = val;
                }
            }
            __syncwarp();
        }
}

// =====================================================================
// Attention v5 (TF32 WMMA, 32-row CTA, no spills):
// 32 q-rows/CTA, key tiles of 64, V chunked 2x128.
// Only 4 persistent accum frags/warp (32 regs) -> fits 2 CTAs/SM @128 regs.
// num/den softmax (no max subtraction), validated round 6.
// smem = 73920 B.
// =====================================================================
#define LDQ 36    // Qst row stride (32 rows + pad)
#define LDK 72    // Kst / SPs row stride (64 keys + pad)
#define LDV 132   // Vs row stride (128 cols + pad)
#define ATT_SMEM (18480 * 4)

__global__ __launch_bounds__(256, 2) void attn_kernel(const float* __restrict__ biases)
{
    extern __shared__ float smem[];
    float* Qst = smem;              // [64 d][LDQ]   Q^T tf32 (rows in cols)
    float* Kst = smem + 2304;       // [64 d][LDK]   K^T tf32
    float* SPs = smem + 6912;       // [32 r][LDK]   S then P
    float* Vs  = smem + 9216;       // [64 k][LDV]   V chunk tf32; O staging
    float* brow= smem + 17664;      // 784
    float* den = smem + 18448;      // 32

    const int bh = blockIdx.y;
    const int b  = bh >> 3;
    const int h  = bh & 7;
    const int n0 = blockIdx.x * 32;
    const int tid  = threadIdx.x;
    const int wid  = tid >> 5;
    const int wm = wid >> 2;        // 0/1: row group of 16
    const int wn = wid & 3;         // 0..3: col group

    const float* Qb = g_Q + (size_t)bh * KDIM * Nseq;
    const float* Kb = g_K + (size_t)bh * KDIM * Nseq;
    const float* Vb = g_V + (size_t)bh * Nseq * VDIM;

    for (int i = tid; i < Nseq; i += 256) brow[i] = biases[h * Nseq + i];
    if (tid < 32) den[tid] = 0.f;

    // load Q^T tile (tf32): Qst[d][r], 64 d x 32 rows
#pragma unroll
    for (int i = 0; i < 2; i++) {
        int s  = tid + i * 256;
        int d  = s >> 3;
        int q4 = (s & 7) << 2;
        float4 v = (n0 + q4 < Nseq)
                 ? *(const float4*)(Qb + (size_t)d * Nseq + n0 + q4)
                 : make_float4(0.f, 0.f, 0.f, 0.f);
        Qst[d * LDQ + q4 + 0] = wmma::__float_to_tf32(v.x);
        Qst[d * LDQ + q4 + 1] = wmma::__float_to_tf32(v.y);
        Qst[d * LDQ + q4 + 2] = wmma::__float_to_tf32(v.z);
        Qst[d * LDQ + q4 + 3] = wmma::__float_to_tf32(v.w);
    }

    // softmax mapping: thread -> row tid>>3 (0..31), cols (tid&7)*8..+7
    const int smr = tid >> 3;
    const int smc = (tid & 7) << 3;
    int rn = n0 + smr;
    int rc = (rn < Nseq) ? rn : (Nseq - 1);
    const int ry = rc / RESW;
    const int rx = rc - ry * RESW;

    // persistent O accum: rows wm*16..+15, cols c*128 + wn*32 + f*16
    wmma::fragment<wmma::accumulator, 16, 16, 8, float> of[2][2];
#pragma unroll
    for (int c = 0; c < 2; c++)
#pragma unroll
        for (int f = 0; f < 2; f++)
            wmma::fill_fragment(of[c][f], 0.f);

    const int NTILE = (Nseq + 63) / 64;   // 13
    for (int kt = 0; kt < NTILE; kt++) {
        const int mbase = kt * 64;
        __syncthreads();   // prior tile's reads of Kst/SPs/Vs complete

        // load K^T tile (tf32): Kst[d][m], 64 d x 64 keys
#pragma unroll
        for (int i = 0; i < 4; i++) {
            int s  = tid + i * 256;
            int d  = s >> 4;
            int q4 = (s & 15) << 2;
            float4 v = (mbase + q4 < Nseq)
                     ? *(const float4*)(Kb + (size_t)d * Nseq + mbase + q4)
                     : make_float4(0.f, 0.f, 0.f, 0.f);
            Kst[d * LDK + q4 + 0] = wmma::__float_to_tf32(v.x);
            Kst[d * LDK + q4 + 1] = wmma::__float_to_tf32(v.y);
            Kst[d * LDK + q4 + 2] = wmma::__float_to_tf32(v.z);
            Kst[d * LDK + q4 + 3] = wmma::__float_to_tf32(v.w);
        }
        __syncthreads();

        // ---- S = Q.K^T : warp (wm,wn) -> S[wm*16..+15][wn*16..+15] ----
        {
            wmma::fragment<wmma::accumulator, 16, 16, 8, float> sf;
            wmma::fill_fragment(sf, 0.f);
#pragma unroll
            for (int kk = 0; kk < KDIM; kk += 8) {
                wmma::fragment<wmma::matrix_a, 16, 16, 8, wmma::precision::tf32, wmma::col_major> af;
                wmma::fragment<wmma::matrix_b, 16, 16, 8, wmma::precision::tf32, wmma::row_major> bf;
                wmma::load_matrix_sync(af, &Qst[kk * LDQ + wm * 16], LDQ);
                wmma::load_matrix_sync(bf, &Kst[kk * LDK + wn * 16], LDK);
                wmma::mma_sync(sf, af, bf, sf);
            }
            wmma::store_matrix_sync(&SPs[(wm * 16) * LDK + wn * 16], sf, LDK,
                                    wmma::mem_row_major);
        }
        __syncthreads();

        // ---- softmax: P = exp(S*scale + bias); accumulate den ----
        {
            float psum = 0.f;
#pragma unroll
            for (int c = 0; c < 8; c++) {
                int m = mbase + smc + c;
                float p = 0.f;
                if (m < Nseq) {
                    int my = m / RESW;
                    int mx = m - my * RESW;
                    int dy = abs(ry - my), dx = abs(rx - mx);
                    float sv = SPs[smr * LDK + smc + c] * SCALEV + brow[dy * RESW + dx];
                    p = wmma::__float_to_tf32(__expf(sv));
                }
                SPs[smr * LDK + smc + c] = p;
                psum += p;
            }
            psum += __shfl_xor_sync(0xffffffffu, psum, 1);
            psum += __shfl_xor_sync(0xffffffffu, psum, 2);
            psum += __shfl_xor_sync(0xffffffffu, psum, 4);
            if ((tid & 7) == 0) den[smr] += psum;
        }
        __syncthreads();

        // ---- PV: O[wm*16..+15][c*128 + wn*32 + f*16] += P.V ----
#pragma unroll
        for (int c = 0; c < 2; c++) {
#pragma unroll
            for (int i = 0; i < 8; i++) {
                int s  = tid + i * 256;
                int mm = s >> 5;
                int c4 = (s & 31) << 2;
                float4 v = (mbase + mm < Nseq)
                         ? *(const float4*)(Vb + (size_t)(mbase + mm) * VDIM + c * 128 + c4)
                         : make_float4(0.f, 0.f, 0.f, 0.f);
                Vs[mm * LDV + c4 + 0] = wmma::__float_to_tf32(v.x);
                Vs[mm * LDV + c4 + 1] = wmma::__float_to_tf32(v.y);
                Vs[mm * LDV + c4 + 2] = wmma::__float_to_tf32(v.z);
                Vs[mm * LDV + c4 + 3] = wmma::__float_to_tf32(v.w);
            }
            __syncthreads();
#pragma unroll
            for (int kk = 0; kk < 64; kk += 8) {
                wmma::fragment<wmma::matrix_a, 16, 16, 8, wmma::precision::tf32, wmma::row_major> pf;
                wmma::load_matrix_sync(pf, &SPs[(wm * 16) * LDK + kk], LDK);
#pragma unroll
                for (int f = 0; f < 2; f++) {
                    wmma::fragment<wmma::matrix_b, 16, 16, 8, wmma::precision::tf32, wmma::row_major> bf;
                    wmma::load_matrix_sync(bf, &Vs[kk * LDV + wn * 32 + f * 16], LDV);
                    wmma::mma_sync(of[c][f], pf, bf, of[c][f]);
                }
            }
            if (c == 0) __syncthreads();   // before overwriting Vs with chunk 1
        }
    }

    // ---- epilogue: stage O, normalize by den, SiLU, store ----
#pragma unroll
    for (int c = 0; c < 2; c++) {
        __syncthreads();
#pragma unroll
        for (int f = 0; f < 2; f++)
            wmma::store_matrix_sync(&Vs[(wm * 16) * LDV + wn * 32 + f * 16],
                                    of[c][f], LDV, wmma::mem_row_major);
        __syncthreads();
        int n = n0 + smr;
        if (n < Nseq) {
            float inv = 1.f / den[smr];
            size_t base = ((size_t)b * Nseq + n) * (Hh * VDIM) + h * VDIM + c * 128;
            int col0 = (tid & 7) << 4;
#pragma unroll
            for (int j = 0; j < 4; j++) {
                int col = col0 + j * 4;
                float4 v = *(const float4*)&Vs[smr * LDV + col];
                float t;
                t = v.x * inv; v.x = t / (1.f + __expf(-t));
                t = v.y * inv; v.y = t / (1.f + __expf(-t));
                t = v.z * inv; v.z = t / (1.f + __expf(-t));
                t = v.w * inv; v.w = t / (1.f + __expf(-t));
                *(float4*)(g_AO + base + col) = v;
            }
        }
    }
}

// =====================================================================
// GEMM 2 (TF32 WMMA): out = BN(silu_out @ proj_w^T)  (round 5, unchanged)
// =====================================================================
__global__ __launch_bounds__(256) void gemm_proj_kernel(
    const float* __restrict__ W,
    const float* __restrict__ gamma, const float* __restrict__ beta,
    const float* __restrict__ mean, const float* __restrict__ var,
    float* __restrict__ out)
{
    __shared__ float As[128][LDA];
    __shared__ float Bs[128][LDA];
    __shared__ float stage[8][16 * 20];

    const int K  = Hh * VDIM;   // 2048
    const float* A = g_AO;
    const int bm = blockIdx.x * 128;
    const int bn = blockIdx.y * 128;
    const int tid  = threadIdx.x;
    const int wid  = tid >> 5;
    const int lane = tid & 31;
    const int wm = wid & 3;
    const int wn = wid >> 2;

    wmma::fragment<wmma::accumulator, 16, 16, 8, float> cf[2][4];
#pragma unroll
    for (int mi = 0; mi < 2; mi++)
#pragma unroll
        for (int ni = 0; ni < 4; ni++)
            wmma::fill_fragment(cf[mi][ni], 0.f);

    for (int k0 = 0; k0 < K; k0 += 32) {
        __syncthreads();
#pragma unroll
        for (int i = 0; i < 4; i++) {
            int s   = tid + i * 256;
            int row = s >> 3;
            int c4  = (s & 7) << 2;
            float4 av = *(const float4*)(A + (size_t)(bm + row) * K + k0 + c4);
            float4 wv = *(const float4*)(W + (size_t)(bn + row) * K + k0 + c4);
            As[row][c4+0] = wmma::__float_to_tf32(av.x);
            As[row][c4+1] = wmma::__float_to_tf32(av.y);
            As[row][c4+2] = wmma::__float_to_tf32(av.z);
            As[row][c4+3] = wmma::__float_to_tf32(av.w);
            Bs[row][c4+0] = wmma::__float_to_tf32(wv.x);
            Bs[row][c4+1] = wmma::__float_to_tf32(wv.y);
            Bs[row][c4+2] = wmma::__float_to_tf32(wv.z);
            Bs[row][c4+3] = wmma::__float_to_tf32(wv.w);
        }
        __syncthreads();

#pragma unroll
        for (int kk = 0; kk < 32; kk += 8) {
            wmma::fragment<wmma::matrix_b, 16, 16, 8, wmma::precision::tf32, wmma::col_major> bf[4];
#pragma unroll
            for (int ni = 0; ni < 4; ni++)
                wmma::load_matrix_sync(bf[ni], &Bs[wn * 64 + ni * 16][kk], LDA);
#pragma unroll
            for (int mi = 0; mi < 2; mi++) {
                wmma::fragment<wmma::matrix_a, 16, 16, 8, wmma::precision::tf32, wmma::row_major> af;
                wmma::load_matrix_sync(af, &As[wm * 32 + mi * 16][kk], LDA);
#pragma unroll
                for (int ni = 0; ni < 4; ni++)
                    wmma::mma_sync(cf[mi][ni], af, bf[ni], cf[mi][ni]);
            }
        }
    }

    float* st = &stage[wid][0];
    const int r0 = lane >> 3;
    const int c0 = (lane & 7) << 1;
#pragma unroll
    for (int mi = 0; mi < 2; mi++)
#pragma unroll
        for (int ni = 0; ni < 4; ni++) {
            wmma::store_matrix_sync(st, cf[mi][ni], 20, wmma::mem_row_major);
            __syncwarp();
#pragma unroll
            for (int rr = 0; rr < 4; rr++) {
                int r = r0 + rr * 4;
                int row = bm + wm * 32 + mi * 16 + r;
#pragma unroll
                for (int cc = 0; cc < 2; cc++) {
                    int c = c0 + cc;
                    int col = bn + wn * 64 + ni * 16 + c;
                    float sc = gamma[col] * rsqrtf(var[col] + EPSV);
                    float sh = beta[col] - mean[col] * sc;
                    out[(size_t)row * DIM + col] = st[r * 20 + c] * sc + sh;
                }
            }
            __syncwarp();
        }
}

// =====================================================================
extern "C" void kernel_launch(void* const* d_in, const int* in_sizes, int n_in,
                              void* d_out, int out_size)
{
    const float* x          = (const float*)d_in[0];
    const float* qkv_w      = (const float*)d_in[1];
    const float* qkv_gamma  = (const float*)d_in[2];
    const float* qkv_beta   = (const float*)d_in[3];
    const float* qkv_mean   = (const float*)d_in[4];
    const float* qkv_var    = (const float*)d_in[5];
    const float* att_bias   = (const float*)d_in[6];
    const float* proj_w     = (const float*)d_in[7];
    const float* proj_gamma = (const float*)d_in[8];
    const float* proj_beta  = (const float*)d_in[9];
    const float* proj_mean  = (const float*)d_in[10];
    const float* proj_var   = (const float*)d_in[11];
    // d_in[12] = bias_idxs: computed analytically in-kernel

    cudaFuncSetAttribute(attn_kernel,
                         cudaFuncAttributeMaxDynamicSharedMemorySize, ATT_SMEM);

    gemm_qkv_kernel<<<dim3(Mrows / 128, QKVO / 128), 256>>>(
        x, qkv_w, qkv_gamma, qkv_beta, qkv_mean, qkv_var);

    attn_kernel<<<dim3((Nseq + 31) / 32, Bsz * Hh), 256, ATT_SMEM>>>(att_bias);

    gemm_proj_kernel<<<dim3(Mrows / 128, DIM / 128), 256>>>(
        proj_w, proj_gamma, proj_beta, proj_mean, proj_var, (float*)d_out);
}

// round 8
// speedup vs baseline: 1.5922x; 1.3580x over previous
#include <cuda_runtime.h>
#include <mma.h>
#include <math.h>

using namespace nvcuda;

// ---------------- problem constants ----------------
#define Bsz   16
#define Nseq  784
#define DIM   512
#define Hh    8
#define KDIM  64
#define VDIM  256
#define RESW  28
#define QKVO  3072      // (2*64+256)*8
#define Mrows (Bsz*Nseq) // 12544
#define EPSV  1e-5f
#define SCALEV 0.125f    // 64^-0.5
#define LDA   36        // smem row stride for BN-GEMM tiles

// ---- packed fp32x2 (Blackwell FFMA2 path; PTX-only) ----
#define FMA_F32X2(d,a,b,c) asm("fma.rn.f32x2 %0, %1, %2, %3;" : "=l"(d) : "l"(a), "l"(b), "l"(c))
#define MUL_F32X2M(d,a,b)  asm("mul.rn.f32x2 %0, %1, %2;" : "=l"(d) : "l"(a), "l"(b))
#define PACK_FF(d,x,y)     asm("mov.b64 %0, {%1, %2};" : "=l"(d) : "f"(x), "f"(y))
#define UNPACK_FF(x,y,d)   asm("mov.b64 {%0, %1}, %2;" : "=f"(x), "=f"(y) : "l"(d))

// ---------------- scratch (device globals; no allocs allowed) ----------------
// Q, K stored TRANSPOSED per (b,h):  [bh][d][n]
__device__ float g_Q[(size_t)Bsz*Hh*KDIM*Nseq];
__device__ float g_K[(size_t)Bsz*Hh*KDIM*Nseq];
__device__ float g_V[(size_t)Bsz*Hh*Nseq*VDIM];
__device__ float g_AO[(size_t)Bsz*Nseq*Hh*VDIM];

// =====================================================================
// GEMM 1 (TF32 WMMA): qkv = BN(x @ qkv_w^T) -> scatter to Q^T/K^T/V
// (verified round 5, unchanged)
// =====================================================================
__global__ __launch_bounds__(256) void gemm_qkv_kernel(
    const float* __restrict__ A, const float* __restrict__ W,
    const float* __restrict__ gamma, const float* __restrict__ beta,
    const float* __restrict__ mean, const float* __restrict__ var)
{
    __shared__ float As[128][LDA];
    __shared__ float Bs[128][LDA];
    __shared__ float stage[8][16 * 20];

    const int K  = DIM;
    const int bm = blockIdx.x * 128;
    const int bn = blockIdx.y * 128;
    const int tid  = threadIdx.x;
    const int wid  = tid >> 5;
    const int lane = tid & 31;
    const int wm = wid & 3;
    const int wn = wid >> 2;

    wmma::fragment<wmma::accumulator, 16, 16, 8, float> cf[2][4];
#pragma unroll
    for (int mi = 0; mi < 2; mi++)
#pragma unroll
        for (int ni = 0; ni < 4; ni++)
            wmma::fill_fragment(cf[mi][ni], 0.f);

    for (int k0 = 0; k0 < K; k0 += 32) {
        __syncthreads();
#pragma unroll
        for (int i = 0; i < 4; i++) {
            int s   = tid + i * 256;
            int row = s >> 3;
            int c4  = (s & 7) << 2;
            float4 av = *(const float4*)(A + (size_t)(bm + row) * K + k0 + c4);
            float4 wv = *(const float4*)(W + (size_t)(bn + row) * K + k0 + c4);
            As[row][c4+0] = wmma::__float_to_tf32(av.x);
            As[row][c4+1] = wmma::__float_to_tf32(av.y);
            As[row][c4+2] = wmma::__float_to_tf32(av.z);
            As[row][c4+3] = wmma::__float_to_tf32(av.w);
            Bs[row][c4+0] = wmma::__float_to_tf32(wv.x);
            Bs[row][c4+1] = wmma::__float_to_tf32(wv.y);
            Bs[row][c4+2] = wmma::__float_to_tf32(wv.z);
            Bs[row][c4+3] = wmma::__float_to_tf32(wv.w);
        }
        __syncthreads();

#pragma unroll
        for (int kk = 0; kk < 32; kk += 8) {
            wmma::fragment<wmma::matrix_b, 16, 16, 8, wmma::precision::tf32, wmma::col_major> bf[4];
#pragma unroll
            for (int ni = 0; ni < 4; ni++)
                wmma::load_matrix_sync(bf[ni], &Bs[wn * 64 + ni * 16][kk], LDA);
#pragma unroll
            for (int mi = 0; mi < 2; mi++) {
                wmma::fragment<wmma::matrix_a, 16, 16, 8, wmma::precision::tf32, wmma::row_major> af;
                wmma::load_matrix_sync(af, &As[wm * 32 + mi * 16][kk], LDA);
#pragma unroll
                for (int ni = 0; ni < 4; ni++)
                    wmma::mma_sync(cf[mi][ni], af, bf[ni], cf[mi][ni]);
            }
        }
    }

    float* st = &stage[wid][0];
    const int r0 = lane >> 3;
    const int c0 = (lane & 7) << 1;
#pragma unroll
    for (int mi = 0; mi < 2; mi++)
#pragma unroll
        for (int ni = 0; ni < 4; ni++) {
            wmma::store_matrix_sync(st, cf[mi][ni], 20, wmma::mem_row_major);
            __syncwarp();
#pragma unroll
            for (int rr = 0; rr < 4; rr++) {
                int r = r0 + rr * 4;
                int row = bm + wm * 32 + mi * 16 + r;
                int b = row / Nseq;
                int n = row - b * Nseq;
#pragma unroll
                for (int cc = 0; cc < 2; cc++) {
                    int c = c0 + cc;
                    int col = bn + wn * 64 + ni * 16 + c;
                    float sc = gamma[col] * rsqrtf(var[col] + EPSV);
                    float sh = beta[col] - mean[col] * sc;
                    float val = st[r * 20 + c] * sc + sh;
                    int h  = col / 384;
                    int rrv = col - h * 384;
                    int bh = b * Hh + h;
                    if (rrv < KDIM)
                        g_Q[((size_t)bh * KDIM + rrv) * Nseq + n] = val;
                    else if (rrv < 2 * KDIM)
                        g_K[((size_t)bh * KDIM + (rrv - KDIM)) * Nseq + n] = val;
                    else
                        g_V[((size_t)bh * Nseq + n) * VDIM + (rrv - 2 * KDIM)] = val;
                }
            }
            __syncwarp();
        }
}

// =====================================================================
// Attention v6: round-3 scalar flash structure, math packed with
// fma.rn.f32x2 (2 MACs/inst). P stored duplicated {p,p} so PV loads one
// LDS.64 broadcast per row. smem = 104768 B, 2 CTAs/SM.
// =====================================================================
#define ATT_SMEM 104768
__global__ __launch_bounds__(256, 2) void attn_kernel(const float* __restrict__ biases)
{
    extern __shared__ float smem[];
    float (*Qst)[68]  = (float(*)[68])smem;                 // [64 d][64 rows+pad]
    float (*Kst)[68]  = (float(*)[68])(smem + 4352);        // [64 d][64 keys+pad]
    float (*Ps2)[130] = (float(*)[130])(smem + 8704);       // [64 rows][128 dup keys+pad]
    float (*Vs)[128]  = (float(*)[128])(smem + 17024);      // [64 keys][128 vcols]
    float* brow = smem + 25216;                             // 784
    float* marr = smem + 26000;                             // 64
    float* larr = smem + 26064;                             // 64
    float* carr = smem + 26128;                             // 64

    const int bh = blockIdx.y;          // b*8+h
    const int b  = bh >> 3;
    const int h  = bh & 7;
    const int n0 = blockIdx.x * 64;
    const int tid  = threadIdx.x;
    const int lane = tid & 31;
    const int w    = tid >> 5;

    const float* Qb = g_Q + (size_t)bh * KDIM * Nseq;
    const float* Kb = g_K + (size_t)bh * KDIM * Nseq;
    const float* Vb = g_V + (size_t)bh * Nseq * VDIM;

    for (int i = tid; i < Nseq; i += 256) brow[i] = biases[h * Nseq + i];
    if (tid < 64) { marr[tid] = -1e30f; larr[tid] = 0.f; }

    // load Q^T tile (64 d x 64 rows)
#pragma unroll
    for (int i = 0; i < 4; i++) {
        int s = tid + i * 256;
        int d = s >> 4;
        int q4 = (s & 15) << 2;
        float4 v = (n0 + q4 < Nseq)
                 ? *(const float4*)(Qb + (size_t)d * Nseq + n0 + q4)
                 : make_float4(0.f, 0.f, 0.f, 0.f);
        *(float4*)&Qst[d][q4] = v;
    }

    const int sr = (tid >> 4) << 2;
    const int sc = (tid & 15) << 2;
    const int ro = w << 3;
    const int co = lane << 2;

    int ry[4], rx[4];
#pragma unroll
    for (int i = 0; i < 4; i++) {
        int n = n0 + sr + i;
        int nc = (n < Nseq) ? n : (Nseq - 1);
        ry[i] = nc / RESW;
        rx[i] = nc - ry[i] * RESW;
    }

    // packed O accumulators: o2[i][0..1]=chunk0 cols co..co+3, [2..3]=chunk1
    unsigned long long o2[8][4];
#pragma unroll
    for (int i = 0; i < 8; i++)
#pragma unroll
        for (int j = 0; j < 4; j++) o2[i][j] = 0ULL;

    const int NTILE = (Nseq + 63) / 64;   // 13
    for (int kt = 0; kt < NTILE; kt++) {
        const int mbase = kt * 64;
        __syncthreads();

        // load K^T tile (64 d x 64 keys)
#pragma unroll
        for (int i = 0; i < 4; i++) {
            int s = tid + i * 256;
            int d = s >> 4;
            int q4 = (s & 15) << 2;
            float4 v = (mbase + q4 < Nseq)
                     ? *(const float4*)(Kb + (size_t)d * Nseq + mbase + q4)
                     : make_float4(0.f, 0.f, 0.f, 0.f);
            *(float4*)&Kst[d][q4] = v;
        }
        __syncthreads();

        // ---- S = Q.K^T, packed over key pairs ----
        unsigned long long s2[4][2];
#pragma unroll
        for (int i = 0; i < 4; i++) { s2[i][0] = 0ULL; s2[i][1] = 0ULL; }
#pragma unroll
        for (int d = 0; d < KDIM; d++) {
            float4 qv = *(const float4*)&Qst[d][sr];
            ulonglong2 kv = *(const ulonglong2*)&Kst[d][sc];
            float qa[4] = {qv.x, qv.y, qv.z, qv.w};
#pragma unroll
            for (int i = 0; i < 4; i++) {
                unsigned long long qq;
                PACK_FF(qq, qa[i], qa[i]);
                FMA_F32X2(s2[i][0], qq, kv.x, s2[i][0]);
                FMA_F32X2(s2[i][1], qq, kv.y, s2[i][1]);
            }
        }
        float s4[4][4];
#pragma unroll
        for (int i = 0; i < 4; i++) {
            UNPACK_FF(s4[i][0], s4[i][1], s2[i][0]);
            UNPACK_FF(s4[i][2], s4[i][3], s2[i][1]);
        }

        // bias + mask
        int myv[4], mxv[4];
        bool mval[4];
#pragma unroll
        for (int j = 0; j < 4; j++) {
            int m = mbase + sc + j;
            mval[j] = (m < Nseq);
            int mc = mval[j] ? m : (Nseq - 1);
            myv[j] = mc / RESW;
            mxv[j] = mc - myv[j] * RESW;
        }
#pragma unroll
        for (int i = 0; i < 4; i++)
#pragma unroll
            for (int j = 0; j < 4; j++) {
                int dy = abs(ry[i] - myv[j]);
                int dx = abs(rx[i] - mxv[j]);
                s4[i][j] = mval[j] ? (s4[i][j] * SCALEV + brow[dy * RESW + dx])
                                   : -1e30f;
            }

        // ---- online softmax; write duplicated P pairs ----
#pragma unroll
        for (int i = 0; i < 4; i++) {
            int r = sr + i;
            float tmax = fmaxf(fmaxf(s4[i][0], s4[i][1]), fmaxf(s4[i][2], s4[i][3]));
#pragma unroll
            for (int off = 8; off; off >>= 1)
                tmax = fmaxf(tmax, __shfl_xor_sync(0xffffffffu, tmax, off));
            float mold = marr[r];
            float mnew = fmaxf(mold, tmax);
            float psum = 0.f;
#pragma unroll
            for (int j = 0; j < 4; j++) {
                float p = __expf(s4[i][j] - mnew);
                *(float2*)&Ps2[r][2 * (sc + j)] = make_float2(p, p);
                psum += p;
            }
#pragma unroll
            for (int off = 8; off; off >>= 1)
                psum += __shfl_xor_sync(0xffffffffu, psum, off);
            if ((tid & 15) == 0) {
                float corr = __expf(mold - mnew);
                larr[r] = larr[r] * corr + psum;
                marr[r] = mnew;
                carr[r] = corr;
            }
        }
        __syncthreads();

        // rescale O by row correction (packed)
#pragma unroll
        for (int i = 0; i < 8; i++) {
            float corr = carr[ro + i];
            unsigned long long cc2;
            PACK_FF(cc2, corr, corr);
#pragma unroll
            for (int j = 0; j < 4; j++)
                MUL_F32X2M(o2[i][j], o2[i][j], cc2);
        }

        // ---- PV over 2 vcol chunks of 128 (packed FMA2) ----
#pragma unroll
        for (int c = 0; c < 2; c++) {
#pragma unroll
            for (int i = 0; i < 8; i++) {
                int s  = tid + i * 256;
                int mm = s >> 5;
                int c4 = (s & 31) << 2;
                float4 v = (mbase + mm < Nseq)
                         ? *(const float4*)(Vb + (size_t)(mbase + mm) * VDIM + c * 128 + c4)
                         : make_float4(0.f, 0.f, 0.f, 0.f);
                *(float4*)&Vs[mm][c4] = v;
            }
            __syncthreads();

            const int jo = c * 2;
#pragma unroll 4
            for (int mm = 0; mm < 64; mm++) {
                ulonglong2 vv = *(const ulonglong2*)&Vs[mm][co];
#pragma unroll
                for (int i = 0; i < 8; i++) {
                    unsigned long long pp =
                        *(const unsigned long long*)&Ps2[ro + i][2 * mm]; // {p,p} broadcast
                    FMA_F32X2(o2[i][jo + 0], pp, vv.x, o2[i][jo + 0]);
                    FMA_F32X2(o2[i][jo + 1], pp, vv.y, o2[i][jo + 1]);
                }
            }
            __syncthreads();
        }
    }

    // ---- epilogue: unpack, normalize, SiLU, store ----
#pragma unroll
    for (int i = 0; i < 8; i++) {
        int n = n0 + ro + i;
        if (n < Nseq) {
            float inv = 1.f / larr[ro + i];
            size_t base = ((size_t)b * Nseq + n) * (Hh * VDIM) + h * VDIM;
            float o[8];
            UNPACK_FF(o[0], o[1], o2[i][0]);
            UNPACK_FF(o[2], o[3], o2[i][1]);
            UNPACK_FF(o[4], o[5], o2[i][2]);
            UNPACK_FF(o[6], o[7], o2[i][3]);
            float4 v0, v1;
            float t;
            t = o[0] * inv; v0.x = t / (1.f + __expf(-t));
            t = o[1] * inv; v0.y = t / (1.f + __expf(-t));
            t = o[2] * inv; v0.z = t / (1.f + __expf(-t));
            t = o[3] * inv; v0.w = t / (1.f + __expf(-t));
            t = o[4] * inv; v1.x = t / (1.f + __expf(-t));
            t = o[5] * inv; v1.y = t / (1.f + __expf(-t));
            t = o[6] * inv; v1.z = t / (1.f + __expf(-t));
            t = o[7] * inv; v1.w = t / (1.f + __expf(-t));
            *(float4*)(g_AO + base + co)       = v0;
            *(float4*)(g_AO + base + 128 + co) = v1;
        }
    }
}

// =====================================================================
// GEMM 2 (TF32 WMMA): out = BN(silu_out @ proj_w^T)  (round 5, unchanged)
// =====================================================================
__global__ __launch_bounds__(256) void gemm_proj_kernel(
    const float* __restrict__ W,
    const float* __restrict__ gamma, const float* __restrict__ beta,
    const float* __restrict__ mean, const float* __restrict__ var,
    float* __restrict__ out)
{
    __shared__ float As[128][LDA];
    __shared__ float Bs[128][LDA];
    __shared__ float stage[8][16 * 20];

    const int K  = Hh * VDIM;   // 2048
    const float* A = g_AO;
    const int bm = blockIdx.x * 128;
    const int bn = blockIdx.y * 128;
    const int tid  = threadIdx.x;
    const int wid  = tid >> 5;
    const int lane = tid & 31;
    const int wm = wid & 3;
    const int wn = wid >> 2;

    wmma::fragment<wmma::accumulator, 16, 16, 8, float> cf[2][4];
#pragma unroll
    for (int mi = 0; mi < 2; mi++)
#pragma unroll
        for (int ni = 0; ni < 4; ni++)
            wmma::fill_fragment(cf[mi][ni], 0.f);

    for (int k0 = 0; k0 < K; k0 += 32) {
        __syncthreads();
#pragma unroll
        for (int i = 0; i < 4; i++) {
            int s   = tid + i * 256;
            int row = s >> 3;
            int c4  = (s & 7) << 2;
            float4 av = *(const float4*)(A + (size_t)(bm + row) * K + k0 + c4);
            float4 wv = *(const float4*)(W + (size_t)(bn + row) * K + k0 + c4);
            As[row][c4+0] = wmma::__float_to_tf32(av.x);
            As[row][c4+1] = wmma::__float_to_tf32(av.y);
            As[row][c4+2] = wmma::__float_to_tf32(av.z);
            As[row][c4+3] = wmma::__float_to_tf32(av.w);
            Bs[row][c4+0] = wmma::__float_to_tf32(wv.x);
            Bs[row][c4+1] = wmma::__float_to_tf32(wv.y);
            Bs[row][c4+2] = wmma::__float_to_tf32(wv.z);
            Bs[row][c4+3] = wmma::__float_to_tf32(wv.w);
        }
        __syncthreads();

#pragma unroll
        for (int kk = 0; kk < 32; kk += 8) {
            wmma::fragment<wmma::matrix_b, 16, 16, 8, wmma::precision::tf32, wmma::col_major> bf[4];
#pragma unroll
            for (int ni = 0; ni < 4; ni++)
                wmma::load_matrix_sync(bf[ni], &Bs[wn * 64 + ni * 16][kk], LDA);
#pragma unroll
            for (int mi = 0; mi < 2; mi++) {
                wmma::fragment<wmma::matrix_a, 16, 16, 8, wmma::precision::tf32, wmma::row_major> af;
                wmma::load_matrix_sync(af, &As[wm * 32 + mi * 16][kk], LDA);
#pragma unroll
                for (int ni = 0; ni < 4; ni++)
                    wmma::mma_sync(cf[mi][ni], af, bf[ni], cf[mi][ni]);
            }
        }
    }

    float* st = &stage[wid][0];
    const int r0 = lane >> 3;
    const int c0 = (lane & 7) << 1;
#pragma unroll
    for (int mi = 0; mi < 2; mi++)
#pragma unroll
        for (int ni = 0; ni < 4; ni++) {
            wmma::store_matrix_sync(st, cf[mi][ni], 20, wmma::mem_row_major);
            __syncwarp();
#pragma unroll
            for (int rr = 0; rr < 4; rr++) {
                int r = r0 + rr * 4;
                int row = bm + wm * 32 + mi * 16 + r;
#pragma unroll
                for (int cc = 0; cc < 2; cc++) {
                    int c = c0 + cc;
                    int col = bn + wn * 64 + ni * 16 + c;
                    float sc = gamma[col] * rsqrtf(var[col] + EPSV);
                    float sh = beta[col] - mean[col] * sc;
                    out[(size_t)row * DIM + col] = st[r * 20 + c] * sc + sh;
                }
            }
            __syncwarp();
        }
}

// =====================================================================
extern "C" void kernel_launch(void* const* d_in, const int* in_sizes, int n_in,
                              void* d_out, int out_size)
{
    const float* x          = (const float*)d_in[0];
    const float* qkv_w      = (const float*)d_in[1];
    const float* qkv_gamma  = (const float*)d_in[2];
    const float* qkv_beta   = (const float*)d_in[3];
    const float* qkv_mean   = (const float*)d_in[4];
    const float* qkv_var    = (const float*)d_in[5];
    const float* att_bias   = (const float*)d_in[6];
    const float* proj_w     = (const float*)d_in[7];
    const float* proj_gamma = (const float*)d_in[8];
    const float* proj_beta  = (const float*)d_in[9];
    const float* proj_mean  = (const float*)d_in[10];
    const float* proj_var   = (const float*)d_in[11];
    // d_in[12] = bias_idxs: computed analytically in-kernel

    cudaFuncSetAttribute(attn_kernel,
                         cudaFuncAttributeMaxDynamicSharedMemorySize, ATT_SMEM);

    gemm_qkv_kernel<<<dim3(Mrows / 128, QKVO / 128), 256>>>(
        x, qkv_w, qkv_gamma, qkv_beta, qkv_mean, qkv_var);

    attn_kernel<<<dim3((Nseq + 63) / 64, Bsz * Hh), 256, ATT_SMEM>>>(att_bias);

    gemm_proj_kernel<<<dim3(Mrows / 128, DIM / 128), 256>>>(
        proj_w, proj_gamma, proj_beta, proj_mean, proj_var, (float*)d_out);
}

// round 10
// speedup vs baseline: 1.9830x; 1.2455x over previous
#include <cuda_runtime.h>
#include <cstdint>
#include <mma.h>
#include <math.h>

using namespace nvcuda;

// ---------------- problem constants ----------------
#define Bsz   16
#define Nseq  784
#define DIM   512
#define Hh    8
#define KDIM  64
#define VDIM  256
#define RESW  28
#define QKVO  3072      // (2*64+256)*8
#define Mrows (Bsz*Nseq) // 12544
#define EPSV  1e-5f
#define SCALEV 0.125f    // 64^-0.5
#define LDA   36        // smem row stride for BN-GEMM tiles

// ---- packed fp32x2 (Blackwell FFMA2 path; PTX-only) ----
#define FMA_F32X2(d,a,b,c) asm("fma.rn.f32x2 %0, %1, %2, %3;" : "=l"(d) : "l"(a), "l"(b), "l"(c))
#define MUL_F32X2M(d,a,b)  asm("mul.rn.f32x2 %0, %1, %2;" : "=l"(d) : "l"(a), "l"(b))
#define PACK_FF(d,x,y)     asm("mov.b64 %0, {%1, %2};" : "=l"(d) : "f"(x), "f"(y))
#define UNPACK_FF(x,y,d)   asm("mov.b64 {%0, %1}, %2;" : "=f"(x), "=f"(y) : "l"(d))

__device__ __forceinline__ void cpa16(unsigned int dst, const void* src) {
    asm volatile("cp.async.cg.shared.global [%0], [%1], 16;" :: "r"(dst), "l"(src));
}
#define CP_COMMIT() asm volatile("cp.async.commit_group;")
#define CP_WAIT0()  asm volatile("cp.async.wait_group 0;")

__device__ __forceinline__ unsigned int smem_u32(const void* p) {
    return (unsigned int)__cvta_generic_to_shared(p);
}

// ---------------- scratch (device globals; no allocs allowed) ----------------
// Q, K stored TRANSPOSED per (b,h):  [bh][d][n]
__device__ float g_Q[(size_t)Bsz*Hh*KDIM*Nseq];
__device__ float g_K[(size_t)Bsz*Hh*KDIM*Nseq];
__device__ float g_V[(size_t)Bsz*Hh*Nseq*VDIM];
__device__ float g_AO[(size_t)Bsz*Nseq*Hh*VDIM];

// =====================================================================
// GEMM 1 (TF32 WMMA): qkv = BN(x @ qkv_w^T) -> scatter to Q^T/K^T/V
// (verified round 5, unchanged)
// =====================================================================
__global__ __launch_bounds__(256) void gemm_qkv_kernel(
    const float* __restrict__ A, const float* __restrict__ W,
    const float* __restrict__ gamma, const float* __restrict__ beta,
    const float* __restrict__ mean, const float* __restrict__ var)
{
    __shared__ float As[128][LDA];
    __shared__ float Bs[128][LDA];
    __shared__ float stage[8][16 * 20];

    const int K  = DIM;
    const int bm = blockIdx.x * 128;
    const int bn = blockIdx.y * 128;
    const int tid  = threadIdx.x;
    const int wid  = tid >> 5;
    const int lane = tid & 31;
    const int wm = wid & 3;
    const int wn = wid >> 2;

    wmma::fragment<wmma::accumulator, 16, 16, 8, float> cf[2][4];
#pragma unroll
    for (int mi = 0; mi < 2; mi++)
#pragma unroll
        for (int ni = 0; ni < 4; ni++)
            wmma::fill_fragment(cf[mi][ni], 0.f);

    for (int k0 = 0; k0 < K; k0 += 32) {
        __syncthreads();
#pragma unroll
        for (int i = 0; i < 4; i++) {
            int s   = tid + i * 256;
            int row = s >> 3;
            int c4  = (s & 7) << 2;
            float4 av = *(const float4*)(A + (size_t)(bm + row) * K + k0 + c4);
            float4 wv = *(const float4*)(W + (size_t)(bn + row) * K + k0 + c4);
            As[row][c4+0] = wmma::__float_to_tf32(av.x);
            As[row][c4+1] = wmma::__float_to_tf32(av.y);
            As[row][c4+2] = wmma::__float_to_tf32(av.z);
            As[row][c4+3] = wmma::__float_to_tf32(av.w);
            Bs[row][c4+0] = wmma::__float_to_tf32(wv.x);
            Bs[row][c4+1] = wmma::__float_to_tf32(wv.y);
            Bs[row][c4+2] = wmma::__float_to_tf32(wv.z);
            Bs[row][c4+3] = wmma::__float_to_tf32(wv.w);
        }
        __syncthreads();

#pragma unroll
        for (int kk = 0; kk < 32; kk += 8) {
            wmma::fragment<wmma::matrix_b, 16, 16, 8, wmma::precision::tf32, wmma::col_major> bf[4];
#pragma unroll
            for (int ni = 0; ni < 4; ni++)
                wmma::load_matrix_sync(bf[ni], &Bs[wn * 64 + ni * 16][kk], LDA);
#pragma unroll
            for (int mi = 0; mi < 2; mi++) {
                wmma::fragment<wmma::matrix_a, 16, 16, 8, wmma::precision::tf32, wmma::row_major> af;
                wmma::load_matrix_sync(af, &As[wm * 32 + mi * 16][kk], LDA);
#pragma unroll
                for (int ni = 0; ni < 4; ni++)
                    wmma::mma_sync(cf[mi][ni], af, bf[ni], cf[mi][ni]);
            }
        }
    }

    float* st = &stage[wid][0];
    const int r0 = lane >> 3;
    const int c0 = (lane & 7) << 1;
#pragma unroll
    for (int mi = 0; mi < 2; mi++)
#pragma unroll
        for (int ni = 0; ni < 4; ni++) {
            wmma::store_matrix_sync(st, cf[mi][ni], 20, wmma::mem_row_major);
            __syncwarp();
#pragma unroll
            for (int rr = 0; rr < 4; rr++) {
                int r = r0 + rr * 4;
                int row = bm + wm * 32 + mi * 16 + r;
                int b = row / Nseq;
                int n = row - b * Nseq;
#pragma unroll
                for (int cc = 0; cc < 2; cc++) {
                    int c = c0 + cc;
                    int col = bn + wn * 64 + ni * 16 + c;
                    float sc = gamma[col] * rsqrtf(var[col] + EPSV);
                    float sh = beta[col] - mean[col] * sc;
                    float val = st[r * 20 + c] * sc + sh;
                    int h  = col / 384;
                    int rrv = col - h * 384;
                    int bh = b * Hh + h;
                    if (rrv < KDIM)
                        g_Q[((size_t)bh * KDIM + rrv) * Nseq + n] = val;
                    else if (rrv < 2 * KDIM)
                        g_K[((size_t)bh * KDIM + (rrv - KDIM)) * Nseq + n] = val;
                    else
                        g_V[((size_t)bh * Nseq + n) * VDIM + (rrv - 2 * KDIM)] = val;
                }
            }
            __syncwarp();
        }
}

// =====================================================================
// Attention v8: cp.async pipelined flash attention.
// 256 thr, 64 q-rows/CTA, 25 key tiles of 32, double-buffered K/V via
// LDGSTS (prefetch t+1 during compute of t), 2 barriers/tile.
// S scalar FFMA; P stored transposed Pt[key][row]; PV row-pair FMA2.
// smem = 113984 B, 2 CTAs/SM.
// =====================================================================
#define NKT 25
#define ATT_SMEM 113984

__global__ __launch_bounds__(256, 2) void attn_kernel(const float* __restrict__ biases)
{
    extern __shared__ float smem[];
    float (*Qst)[68]      = (float(*)[68])smem;                     // [64 d][64 r+pad]
    float (*Kst)[64][36]  = (float(*)[64][36])(smem + 4352);        // [2][64 d][32 k+pad]
    float (*Pt)[68]       = (float(*)[68])(smem + 8960);            // [32 k][64 r+pad]
    float (*Vs)[32][256]  = (float(*)[32][256])(smem + 11136);      // [2][32 k][256]
    float* brow = smem + 27520;                                     // 784
    float* marr = smem + 28304;                                     // 64
    float* larr = smem + 28368;                                     // 64
    float* carr = smem + 28432;                                     // 64

    const int bh = blockIdx.y;
    const int b  = bh >> 3;
    const int h  = bh & 7;
    const int n0 = blockIdx.x * 64;
    const int tid  = threadIdx.x;
    const int lane = tid & 31;
    const int w    = tid >> 5;

    const float* Qb = g_Q + (size_t)bh * KDIM * Nseq;
    const float* Kb = g_K + (size_t)bh * KDIM * Nseq;
    const float* Vb = g_V + (size_t)bh * Nseq * VDIM;

    // ---- prologue: prefetch tile 0, load Q/brow, init stats ----
    {
        // K tile 0 -> buf 0  (512 granules of 16B)
#pragma unroll
        for (int i = 0; i < 2; i++) {
            int g = tid + i * 256;
            int d = g >> 3, c = (g & 7) << 2;
            cpa16(smem_u32(&Kst[0][d][c]), Kb + (size_t)d * Nseq + c);
        }
        // V tile 0 -> buf 0 (2048 granules)
#pragma unroll
        for (int i = 0; i < 8; i++) {
            int g = tid + i * 256;
            int mm = g >> 6, c = (g & 63) << 2;
            cpa16(smem_u32(&Vs[0][mm][c]), Vb + (size_t)mm * VDIM + c);
        }
        CP_COMMIT();
    }

    for (int i = tid; i < Nseq; i += 256) brow[i] = biases[h * Nseq + i];
    if (tid < 64) { marr[tid] = -1e30f; larr[tid] = 0.f; }

    // load Q^T tile (64 d x 64 rows), regular loads
#pragma unroll
    for (int i = 0; i < 4; i++) {
        int s = tid + i * 256;
        int d = s >> 4;
        int q4 = (s & 15) << 2;
        float4 v = (n0 + q4 < Nseq)
                 ? *(const float4*)(Qb + (size_t)d * Nseq + n0 + q4)
                 : make_float4(0.f, 0.f, 0.f, 0.f);
        *(float4*)&Qst[d][q4] = v;
    }

    // mappings
    const int sr = (tid >> 4) << 2;     // S rows (4)
    const int sc = (tid & 15) << 1;     // S keys (2)
    const int ro = w << 3;              // PV rows (8)
    const int co = lane << 2;           // PV cols (4 + 4 at +128)

    int ry[4], rx[4];
#pragma unroll
    for (int i = 0; i < 4; i++) {
        int n = n0 + sr + i;
        int nc = (n < Nseq) ? n : (Nseq - 1);
        ry[i] = nc / RESW;
        rx[i] = nc - ry[i] * RESW;
    }

    // packed O: o2[k][c] = {rows ro+2k, ro+2k+1} x col (c<4 ? co+c : 128+co+c-4)
    unsigned long long o2[4][8];
#pragma unroll
    for (int k = 0; k < 4; k++)
#pragma unroll
        for (int c = 0; c < 8; c++) o2[k][c] = 0ULL;

    for (int kt = 0; kt < NKT; kt++) {
        const int buf = kt & 1;
        const int mbase = kt * 32;

        CP_WAIT0();
        __syncthreads();   // tile kt data visible; all warps past PV(kt-1)

        // prefetch tile kt+1 into other buffer (overlaps with compute below)
        if (kt + 1 < NKT) {
            const int nb = mbase + 32;
#pragma unroll
            for (int i = 0; i < 2; i++) {
                int g = tid + i * 256;
                int d = g >> 3, c = (g & 7) << 2;
                if (nb + c < Nseq)
                    cpa16(smem_u32(&Kst[buf ^ 1][d][c]),
                          Kb + (size_t)d * Nseq + nb + c);
                else
                    *(float4*)&Kst[buf ^ 1][d][c] = make_float4(0.f, 0.f, 0.f, 0.f);
            }
#pragma unroll
            for (int i = 0; i < 8; i++) {
                int g = tid + i * 256;
                int mm = g >> 6, c = (g & 63) << 2;
                if (nb + mm < Nseq)
                    cpa16(smem_u32(&Vs[buf ^ 1][mm][c]),
                          Vb + (size_t)(nb + mm) * VDIM + c);
                else
                    *(float4*)&Vs[buf ^ 1][mm][c] = make_float4(0.f, 0.f, 0.f, 0.f);
            }
        }
        CP_COMMIT();

        // ---- S = Q.K^T (4 rows x 2 keys per thread) ----
        float s4[4][2];
#pragma unroll
        for (int i = 0; i < 4; i++) { s4[i][0] = 0.f; s4[i][1] = 0.f; }
#pragma unroll
        for (int d = 0; d < KDIM; d++) {
            float4 qv = *(const float4*)&Qst[d][sr];
            float2 kv = *(const float2*)&Kst[buf][d][sc];
            s4[0][0] += qv.x * kv.x;  s4[0][1] += qv.x * kv.y;
            s4[1][0] += qv.y * kv.x;  s4[1][1] += qv.y * kv.y;
            s4[2][0] += qv.z * kv.x;  s4[2][1] += qv.z * kv.y;
            s4[3][0] += qv.w * kv.x;  s4[3][1] += qv.w * kv.y;
        }

        // bias + mask for the 2 keys
        int m0 = mbase + sc, m1 = m0 + 1;
        bool v0 = (m0 < Nseq), v1 = (m1 < Nseq);
        int mc0 = v0 ? m0 : (Nseq - 1);
        int mc1 = v1 ? m1 : (Nseq - 1);
        int my0 = mc0 / RESW, mx0 = mc0 - my0 * RESW;
        int my1 = mc1 / RESW, mx1 = mc1 - my1 * RESW;
#pragma unroll
        for (int i = 0; i < 4; i++) {
            s4[i][0] = v0 ? (s4[i][0] * SCALEV + brow[abs(ry[i]-my0) * RESW + abs(rx[i]-mx0)]) : -1e30f;
            s4[i][1] = v1 ? (s4[i][1] * SCALEV + brow[abs(ry[i]-my1) * RESW + abs(rx[i]-mx1)]) : -1e30f;
        }

        // ---- online softmax; write P transposed ----
        float p0v[4], p1v[4];
#pragma unroll
        for (int i = 0; i < 4; i++) {
            int r = sr + i;
            float tmax = fmaxf(s4[i][0], s4[i][1]);
#pragma unroll
            for (int off = 8; off; off >>= 1)
                tmax = fmaxf(tmax, __shfl_xor_sync(0xffffffffu, tmax, off));
            float mold = marr[r];
            float mnew = fmaxf(mold, tmax);
            float p0 = __expf(s4[i][0] - mnew);
            float p1 = __expf(s4[i][1] - mnew);
            p0v[i] = p0; p1v[i] = p1;
            float psum = p0 + p1;
#pragma unroll
            for (int off = 8; off; off >>= 1)
                psum += __shfl_xor_sync(0xffffffffu, psum, off);
            if ((tid & 15) == 0) {
                float corr = __expf(mold - mnew);
                larr[r] = larr[r] * corr + psum;
                marr[r] = mnew;
                carr[r] = corr;
            }
        }
        *(float4*)&Pt[sc][sr]     = make_float4(p0v[0], p0v[1], p0v[2], p0v[3]);
        *(float4*)&Pt[sc + 1][sr] = make_float4(p1v[0], p1v[1], p1v[2], p1v[3]);
        __syncthreads();   // Pt + carr ready

        // ---- rescale O by row-pair corr ----
#pragma unroll
        for (int k = 0; k < 4; k++) {
            unsigned long long c2 = *(const unsigned long long*)&carr[ro + 2 * k];
#pragma unroll
            for (int c = 0; c < 8; c++)
                MUL_F32X2M(o2[k][c], o2[k][c], c2);
        }

        // ---- PV: row-pair packed FMA2 over 32 keys ----
#pragma unroll 2
        for (int mm = 0; mm < 32; mm++) {
            ulonglong2 pA = *(const ulonglong2*)&Pt[mm][ro];       // rows ro..ro+3 (2 pairs)
            ulonglong2 pB = *(const ulonglong2*)&Pt[mm][ro + 4];   // rows ro+4..ro+7
            unsigned long long p2[4] = {pA.x, pA.y, pB.x, pB.y};
            float4 va = *(const float4*)&Vs[buf][mm][co];
            float4 vb = *(const float4*)&Vs[buf][mm][128 + co];
            unsigned long long vd[8];
            PACK_FF(vd[0], va.x, va.x); PACK_FF(vd[1], va.y, va.y);
            PACK_FF(vd[2], va.z, va.z); PACK_FF(vd[3], va.w, va.w);
            PACK_FF(vd[4], vb.x, vb.x); PACK_FF(vd[5], vb.y, vb.y);
            PACK_FF(vd[6], vb.z, vb.z); PACK_FF(vd[7], vb.w, vb.w);
#pragma unroll
            for (int k = 0; k < 4; k++)
#pragma unroll
                for (int c = 0; c < 8; c++)
                    FMA_F32X2(o2[k][c], p2[k], vd[c], o2[k][c]);
        }
        // bottom barrier not needed: next iteration's top __syncthreads
        // (after CP_WAIT0) orders PV(kt) before prefetch writes of kt+2.
    }

    // ---- epilogue: unpack row pairs, normalize, SiLU, store ----
#pragma unroll
    for (int k = 0; k < 4; k++) {
        float lo[8], hi[8];
#pragma unroll
        for (int c = 0; c < 8; c++) UNPACK_FF(lo[c], hi[c], o2[k][c]);
        int r0i = ro + 2 * k;
#pragma unroll
        for (int half = 0; half < 2; half++) {
            int r = r0i + half;
            int n = n0 + r;
            if (n < Nseq) {
                float inv = 1.f / larr[r];
                const float* src = half ? hi : lo;
                size_t base = ((size_t)b * Nseq + n) * (Hh * VDIM) + h * VDIM;
                float4 vv0, vv1;
                float t;
                t = src[0] * inv; vv0.x = t / (1.f + __expf(-t));
                t = src[1] * inv; vv0.y = t / (1.f + __expf(-t));
                t = src[2] * inv; vv0.z = t / (1.f + __expf(-t));
                t = src[3] * inv; vv0.w = t / (1.f + __expf(-t));
                t = src[4] * inv; vv1.x = t / (1.f + __expf(-t));
                t = src[5] * inv; vv1.y = t / (1.f + __expf(-t));
                t = src[6] * inv; vv1.z = t / (1.f + __expf(-t));
                t = src[7] * inv; vv1.w = t / (1.f + __expf(-t));
                *(float4*)(g_AO + base + co)       = vv0;
                *(float4*)(g_AO + base + 128 + co) = vv1;
            }
        }
    }
}

// =====================================================================
// GEMM 2 (TF32 WMMA): out = BN(silu_out @ proj_w^T)  (round 5, unchanged)
// =====================================================================
__global__ __launch_bounds__(256) void gemm_proj_kernel(
    const float* __restrict__ W,
    const float* __restrict__ gamma, const float* __restrict__ beta,
    const float* __restrict__ mean, const float* __restrict__ var,
    float* __restrict__ out)
{
    __shared__ float As[128][LDA];
    __shared__ float Bs[128][LDA];
    __shared__ float stage[8][16 * 20];

    const int K  = Hh * VDIM;   // 2048
    const float* A = g_AO;
    const int bm = blockIdx.x * 128;
    const int bn = blockIdx.y * 128;
    const int tid  = threadIdx.x;
    const int wid  = tid >> 5;
    const int lane = tid & 31;
    const int wm = wid & 3;
    const int wn = wid >> 2;

    wmma::fragment<wmma::accumulator, 16, 16, 8, float> cf[2][4];
#pragma unroll
    for (int mi = 0; mi < 2; mi++)
#pragma unroll
        for (int ni = 0; ni < 4; ni++)
            wmma::fill_fragment(cf[mi][ni], 0.f);

    for (int k0 = 0; k0 < K; k0 += 32) {
        __syncthreads();
#pragma unroll
        for (int i = 0; i < 4; i++) {
            int s   = tid + i * 256;
            int row = s >> 3;
            int c4  = (s & 7) << 2;
            float4 av = *(const float4*)(A + (size_t)(bm + row) * K + k0 + c4);
            float4 wv = *(const float4*)(W + (size_t)(bn + row) * K + k0 + c4);
            As[row][c4+0] = wmma::__float_to_tf32(av.x);
            As[row][c4+1] = wmma::__float_to_tf32(av.y);
            As[row][c4+2] = wmma::__float_to_tf32(av.z);
            As[row][c4+3] = wmma::__float_to_tf32(av.w);
            Bs[row][c4+0] = wmma::__float_to_tf32(wv.x);
            Bs[row][c4+1] = wmma::__float_to_tf32(wv.y);
            Bs[row][c4+2] = wmma::__float_to_tf32(wv.z);
            Bs[row][c4+3] = wmma::__float_to_tf32(wv.w);
        }
        __syncthreads();

#pragma unroll
        for (int kk = 0; kk < 32; kk += 8) {
            wmma::fragment<wmma::matrix_b, 16, 16, 8, wmma::precision::tf32, wmma::col_major> bf[4];
#pragma unroll
            for (int ni = 0; ni < 4; ni++)
                wmma::load_matrix_sync(bf[ni], &Bs[wn * 64 + ni * 16][kk], LDA);
#pragma unroll
            for (int mi = 0; mi < 2; mi++) {
                wmma::fragment<wmma::matrix_a, 16, 16, 8, wmma::precision::tf32, wmma::row_major> af;
                wmma::load_matrix_sync(af, &As[wm * 32 + mi * 16][kk], LDA);
#pragma unroll
                for (int ni = 0; ni < 4; ni++)
                    wmma::mma_sync(cf[mi][ni], af, bf[ni], cf[mi][ni]);
            }
        }
    }

    float* st = &stage[wid][0];
    const int r0 = lane >> 3;
    const int c0 = (lane & 7) << 1;
#pragma unroll
    for (int mi = 0; mi < 2; mi++)
#pragma unroll
        for (int ni = 0; ni < 4; ni++) {
            wmma::store_matrix_sync(st, cf[mi][ni], 20, wmma::mem_row_major);
            __syncwarp();
#pragma unroll
            for (int rr = 0; rr < 4; rr++) {
                int r = r0 + rr * 4;
                int row = bm + wm * 32 + mi * 16 + r;
#pragma unroll
                for (int cc = 0; cc < 2; cc++) {
                    int c = c0 + cc;
                    int col = bn + wn * 64 + ni * 16 + c;
                    float sc = gamma[col] * rsqrtf(var[col] + EPSV);
                    float sh = beta[col] - mean[col] * sc;
                    out[(size_t)row * DIM + col] = st[r * 20 + c] * sc + sh;
                }
            }
            __syncwarp();
        }
}

// =====================================================================
extern "C" void kernel_launch(void* const* d_in, const int* in_sizes, int n_in,
                              void* d_out, int out_size)
{
    const float* x          = (const float*)d_in[0];
    const float* qkv_w      = (const float*)d_in[1];
    const float* qkv_gamma  = (const float*)d_in[2];
    const float* qkv_beta   = (const float*)d_in[3];
    const float* qkv_mean   = (const float*)d_in[4];
    const float* qkv_var    = (const float*)d_in[5];
    const float* att_bias   = (const float*)d_in[6];
    const float* proj_w     = (const float*)d_in[7];
    const float* proj_gamma = (const float*)d_in[8];
    const float* proj_beta  = (const float*)d_in[9];
    const float* proj_mean  = (const float*)d_in[10];
    const float* proj_var   = (const float*)d_in[11];
    // d_in[12] = bias_idxs: computed analytically in-kernel

    cudaFuncSetAttribute(attn_kernel,
                         cudaFuncAttributeMaxDynamicSharedMemorySize, ATT_SMEM);

    gemm_qkv_kernel<<<dim3(Mrows / 128, QKVO / 128), 256>>>(
        x, qkv_w, qkv_gamma, qkv_beta, qkv_mean, qkv_var);

    attn_kernel<<<dim3((Nseq + 63) / 64, Bsz * Hh), 256, ATT_SMEM>>>(att_bias);

    gemm_proj_kernel<<<dim3(Mrows / 128, DIM / 128), 256>>>(
        proj_w, proj_gamma, proj_beta, proj_mean, proj_var, (float*)d_out);
}